// round 9
// baseline (speedup 1.0000x reference)
#include <cuda_runtime.h>
#include <cstdint>

// ---------------------------------------------------------------------------
// Quan_adder2d, single fused kernel.
// out[n,f,ho,wo] = -sum_{c,i,j} | qw[f,c,i,j] - qx[n,c,ho+i-1,wo+j-1] |
// Integer min-trick on the global 16-bit x grid:
//   sum|.| = s * (W_SUM[f] + X_SUM[win] - 2*sum min(w_int, x_int))
// Blocks 0..31: x minmax partials.  32..33: W quant/regrid/pack (spin on
// minmax).  34..257: 224 work blocks (28 ho x 4 n x 2 f-half), which stage
// raw x during the prep phase and spin on prep completion.
// ---------------------------------------------------------------------------

#define N_BATCH 4
#define C_IN    64
#define HW      28
#define F_OUT   64
#define KDIM    576
#define QX_MAX  65535.0f
#define QW_MAX  255.0f

#define MMB     32
#define NWB     2
#define PREP    (MMB + NWB)     // 34
#define WB      224
#define GRID    (PREP + WB)     // 258
#define THREADS 448
#define SLICES  8
#define CPP     4
#define TPS     56              // 8 fgrp x 7 wog

__device__ float    g_bmin[MMB];
__device__ float    g_bmax[MMB];
__device__ unsigned g_cnt  = 0;
__device__ unsigned g_done = 0;
__device__ unsigned g_fin  = 0;
__device__ float    g_sprm[2];            // xscale, xzp
__device__ unsigned g_wsum[F_OUT];
__device__ unsigned g_swi[2 * 288 * 32];  // [fhalf][k'][f'] packed u16x2

__device__ __forceinline__ unsigned minu2(unsigned a, unsigned b) {
    unsigned r;
    asm("min.u16x2 %0, %1, %2;" : "=r"(r) : "r"(a), "r"(b));
    return r;
}
#define DPB 0x00000101u   // dp2a byte pair (1,1): sums both u16 halves

// smem layout (u32 units). Work path: SWI | SXI | union(SXR raw x floats,
// RED+RPART+RS). Prep W path: [32][577] floats (largest -> sets total).
#define SWI_OFF   0         // 9216
#define SXI_OFF   9216      // 3072
#define UN_OFF    12288
#define RED_OFF   12288     // 3584 (written after mainloop; SXR dead)
#define RPART_OFF 15872     // 240
#define RS_OFF    16112     // 30
#define SMEM_U32  18464     // prep needs 32*577
#define SMEM_BYTES (SMEM_U32 * 4)   // 73856

__global__ void __launch_bounds__(THREADS, 2)
k_fused(const float* __restrict__ x, const float* __restrict__ W,
        float* __restrict__ out) {
    const int tid = threadIdx.x;
    extern __shared__ unsigned smem[];

    // ======================= x min/max partial blocks =======================
    if (blockIdx.x < MMB) {
        const float4* x4 = (const float4*)x;
        const int n4 = (N_BATCH * C_IN * HW * HW) / 4;
        float mn = 1e30f, mx = -1e30f;
        for (int i = blockIdx.x * THREADS + tid; i < n4; i += MMB * THREADS) {
            float4 v = x4[i];
            mn = fminf(fminf(fminf(mn, v.x), v.y), fminf(v.z, v.w));
            mx = fmaxf(fmaxf(fmaxf(mx, v.x), v.y), fmaxf(v.z, v.w));
        }
        #pragma unroll
        for (int o = 16; o > 0; o >>= 1) {
            mn = fminf(mn, __shfl_xor_sync(0xffffffffu, mn, o));
            mx = fmaxf(mx, __shfl_xor_sync(0xffffffffu, mx, o));
        }
        __shared__ float smn[16], smx[16];
        int warp = tid >> 5, lane = tid & 31;
        if (lane == 0) { smn[warp] = mn; smx[warp] = mx; }
        __syncthreads();
        if (tid < 32) {
            mn = (tid < 14) ? smn[tid] : 1e30f;
            mx = (tid < 14) ? smx[tid] : -1e30f;
            #pragma unroll
            for (int o = 16; o > 0; o >>= 1) {
                mn = fminf(mn, __shfl_xor_sync(0xffffffffu, mn, o));
                mx = fmaxf(mx, __shfl_xor_sync(0xffffffffu, mx, o));
            }
            if (tid == 0) {
                g_bmin[blockIdx.x] = mn;
                g_bmax[blockIdx.x] = mx;
                __threadfence();
                atomicAdd(&g_cnt, 1u);
            }
        }
        return;
    }

    // ============================ W prep blocks =============================
    if (blockIdx.x < PREP) {
        const int b    = blockIdx.x - MMB;   // 0,1 -> f half
        float*    sqf  = (float*)smem;       // [32][577]
        const int warp = tid >> 5;           // 0..13
        const int lane = tid & 31;

        // phase 1: per-channel quant-dequant (no x params needed)
        for (int fl = warp; fl < 32; fl += 14) {
            const float* wf = W + (b * 32 + fl) * KDIM;
            float v[18];
            float mn = 1e30f, mx = -1e30f;
            #pragma unroll
            for (int t = 0; t < 18; ++t) {
                v[t] = wf[lane + t * 32];
                mn = fminf(mn, v[t]);
                mx = fmaxf(mx, v[t]);
            }
            #pragma unroll
            for (int o = 16; o > 0; o >>= 1) {
                mn = fminf(mn, __shfl_xor_sync(0xffffffffu, mn, o));
                mx = fmaxf(mx, __shfl_xor_sync(0xffffffffu, mx, o));
            }
            float scale = fmaxf(__fdiv_rn(mx - mn, QW_MAX), 1e-12f);
            float zp    = rintf(__fdiv_rn(-mn, scale));
            #pragma unroll
            for (int t = 0; t < 18; ++t) {
                float q = fminf(fmaxf(rintf(__fdiv_rn(v[t], scale)) + zp, 0.0f),
                                QW_MAX);
                sqf[fl * 577 + lane + t * 32] = (q - zp) * scale;
            }
        }

        // phase 2: wait for minmax, finalize activation params
        __shared__ float xs_s[2];
        if (tid == 0) {
            while (atomicAdd(&g_cnt, 0u) < (unsigned)MMB) __nanosleep(64);
            float xmn = 1e30f, xmx = -1e30f;
            #pragma unroll 8
            for (int i = 0; i < MMB; ++i) {
                xmn = fminf(xmn, g_bmin[i]);
                xmx = fmaxf(xmx, g_bmax[i]);
            }
            float xs = fmaxf(__fdiv_rn(xmx - xmn, QX_MAX), 1e-12f);
            xs_s[0] = xs;
            xs_s[1] = rintf(__fdiv_rn(-xmn, xs));
            if (b == 0) { g_sprm[0] = xs_s[0]; g_sprm[1] = xs_s[1]; }
        }
        __syncthreads();
        const float invs = __fdiv_rn(1.0f, xs_s[0]);
        const float xzp  = xs_s[1];

        // phase 3: regrid to x grid, pack pairs (k', k'+288), wsum
        for (int fl = warp; fl < 32; fl += 14) {
            float v[18];
            #pragma unroll
            for (int t = 0; t < 18; ++t)
                v[t] = sqf[fl * 577 + lane + t * 32];
            unsigned wq[18];
            #pragma unroll
            for (int t = 0; t < 18; ++t)
                wq[t] = (unsigned)fminf(fmaxf(rintf(v[t] * invs) + xzp, 0.0f),
                                        65535.0f);
            unsigned ssum = 0;
            #pragma unroll
            for (int t = 0; t < 9; ++t) {
                unsigned p = wq[t] | (wq[t + 9] << 16);
                ((unsigned*)sqf)[fl * 577 + lane + t * 32] = p;
                ssum = __dp2a_lo(p, DPB, ssum);
            }
            #pragma unroll
            for (int o = 16; o > 0; o >>= 1)
                ssum += __shfl_xor_sync(0xffffffffu, ssum, o);
            if (lane == 0) g_wsum[b * 32 + fl] = ssum;
        }
        __syncthreads();

        // phase 4: transposed coalesced store g_swi[b][k'][f']
        const int j = tid & 31;
        for (int k2 = tid >> 5; k2 < 288; k2 += 14)
            g_swi[b * 9216 + k2 * 32 + j] = ((unsigned*)sqf)[j * 577 + k2];
        __threadfence();
        __syncthreads();
        if (tid == 0) atomicAdd(&g_done, 1u);
        return;
    }

    // ============================= work blocks ==============================
    const int wb = blockIdx.x - PREP;
    const int ho = wb % 28;
    const int nz = wb / 28;
    const int n  = nz & 3;
    const int fh = nz >> 2;

    unsigned* swi   = smem + SWI_OFF;
    unsigned* sxi   = smem + SXI_OFF;
    float*    sxr   = (float*)(smem + UN_OFF);
    uint4*    red   = (uint4*)(smem + RED_OFF);
    unsigned* rpart = smem + RPART_OFF;
    unsigned* rs    = smem + RS_OFF;

    // pass 1: raw x staging (overlaps the prep phase)
    for (int idx = tid; idx < 5760; idx += THREADS) {
        int c   = idx / 90;
        int rem = idx - c * 90;
        int i   = rem / 30;
        int col = rem - i * 30;
        int h   = ho + i - 1;
        int w   = col - 1;
        float v = 0.0f;
        if ((unsigned)h < (unsigned)HW && (unsigned)w < (unsigned)HW)
            v = x[((n * C_IN + c) * HW + h) * HW + w];
        sxr[idx] = v;
    }

    // spin for prep completion
    if (tid == 0) {
        while (atomicAdd(&g_done, 0u) < (unsigned)NWB) __nanosleep(64);
    }
    __syncthreads();

    const float s  = g_sprm[0];
    const float zp = g_sprm[1];

    // stage packed W half (L2 resident)
    {
        const uint4* gsrc = (const uint4*)(g_swi + fh * 9216);
        uint4*       sdst = (uint4*)swi;
        for (int i = tid; i < 2304; i += THREADS) sdst[i] = gsrc[i];
    }

    // pass 2: quantize + pack x (quant(0) == zp handles padding exactly)
    for (int idx = tid; idx < 2880; idx += THREADS) {
        int c   = idx / 90;
        int rem = idx - c * 90;
        int i   = rem / 30;
        int col = rem - i * 30;
        float a  = sxr[c * 90 + i * 30 + col];
        float bb = sxr[(c + 32) * 90 + i * 30 + col];
        unsigned vlo = (unsigned)fminf(fmaxf(rintf(__fdiv_rn(a, s)) + zp, 0.0f),
                                       QX_MAX);
        unsigned vhi = (unsigned)fminf(fmaxf(rintf(__fdiv_rn(bb, s)) + zp, 0.0f),
                                       QX_MAX);
        sxi[c * 96 + i * 32 + col] = vlo | (vhi << 16);
    }
    __syncthreads();

    // x window column-sum partials (X_SUM correction); sxr is dead now
    if (tid < 240) {
        int col = tid >> 3;
        int p   = tid & 7;
        unsigned ssum = 0;
        #pragma unroll
        for (int cc = 0; cc < 4; ++cc)
            #pragma unroll
            for (int i = 0; i < 3; ++i)
                ssum = __dp2a_lo(sxi[(p * 4 + cc) * 96 + i * 32 + col], DPB, ssum);
        rpart[col * 8 + p] = ssum;
    }

    // ---- main loop ----
    const int slice = tid / TPS;
    const int t     = tid - slice * TPS;
    const int fgrp  = t & 7;
    const int wog   = t >> 3;
    const int f0    = fgrp * 4;
    const int wo0   = wog * 4;
    const int cp0   = slice * CPP;

    unsigned acc[4][4];
    #pragma unroll
    for (int a = 0; a < 4; ++a)
        #pragma unroll
        for (int b2 = 0; b2 < 4; ++b2) acc[a][b2] = 0u;

    const unsigned* xrow = sxi + cp0 * 96;
    const unsigned* wrow = swi + cp0 * 9 * 32 + f0;

    #pragma unroll
    for (int cp = 0; cp < CPP; ++cp) {
        #pragma unroll
        for (int i = 0; i < 3; ++i) {
            uint4 wp0 = *(const uint4*)(wrow + (i * 3 + 0) * 32);
            uint4 wp1 = *(const uint4*)(wrow + (i * 3 + 1) * 32);
            uint4 wp2 = *(const uint4*)(wrow + (i * 3 + 2) * 32);
            const unsigned* xr = xrow + i * 32 + wo0;
            uint4 xa = *(const uint4*)xr;
            uint2 xb = *(const uint2*)(xr + 4);
            unsigned xsv[6] = { xa.x, xa.y, xa.z, xa.w, xb.x, xb.y };
            #pragma unroll
            for (int k = 0; k < 4; ++k) {
                unsigned x0 = xsv[k], x1 = xsv[k + 1], x2 = xsv[k + 2];
                acc[0][k] = __dp2a_lo(minu2(wp0.x, x0), DPB, acc[0][k]);
                acc[1][k] = __dp2a_lo(minu2(wp0.y, x0), DPB, acc[1][k]);
                acc[2][k] = __dp2a_lo(minu2(wp0.z, x0), DPB, acc[2][k]);
                acc[3][k] = __dp2a_lo(minu2(wp0.w, x0), DPB, acc[3][k]);
                acc[0][k] = __dp2a_lo(minu2(wp1.x, x1), DPB, acc[0][k]);
                acc[1][k] = __dp2a_lo(minu2(wp1.y, x1), DPB, acc[1][k]);
                acc[2][k] = __dp2a_lo(minu2(wp1.z, x1), DPB, acc[2][k]);
                acc[3][k] = __dp2a_lo(minu2(wp1.w, x1), DPB, acc[3][k]);
                acc[0][k] = __dp2a_lo(minu2(wp2.x, x2), DPB, acc[0][k]);
                acc[1][k] = __dp2a_lo(minu2(wp2.y, x2), DPB, acc[1][k]);
                acc[2][k] = __dp2a_lo(minu2(wp2.z, x2), DPB, acc[2][k]);
                acc[3][k] = __dp2a_lo(minu2(wp2.w, x2), DPB, acc[3][k]);
            }
        }
        xrow += 96;
        wrow += 9 * 32;
    }

    uint4 va[4];
    #pragma unroll
    for (int fl = 0; fl < 4; ++fl)
        va[fl] = make_uint4(acc[fl][0], acc[fl][1], acc[fl][2], acc[fl][3]);

#define RSLOT(sl, fl) red[(((sl) * TPS + t) << 2) + (fl)]
#define RADD(sl)                                                  \
    { _Pragma("unroll") for (int fl = 0; fl < 4; ++fl) {          \
        uint4 o = RSLOT(sl, fl);                                  \
        va[fl].x += o.x; va[fl].y += o.y;                         \
        va[fl].z += o.z; va[fl].w += o.w; } }
#define RSTORE(sl)                                                \
    { _Pragma("unroll") for (int fl = 0; fl < 4; ++fl) RSLOT(sl, fl) = va[fl]; }

    // 8 -> 4 -> 2 -> 1 (rs finalized in parallel)
    if (slice >= 4) RSTORE(slice - 4);
    if (tid < 30) {
        unsigned ssum = 0;
        #pragma unroll
        for (int p = 0; p < 8; ++p) ssum += rpart[tid * 8 + p];
        rs[tid] = ssum;
    }
    __syncthreads();
    if (slice < 4) RADD(slice);
    __syncthreads();
    if (slice == 2 || slice == 3) RSTORE(slice - 2);
    __syncthreads();
    if (slice < 2) RADD(slice);
    __syncthreads();
    if (slice == 1) RSTORE(0);
    __syncthreads();
    if (slice == 0) {
        RADD(0);
        int xsum[4];
        #pragma unroll
        for (int k = 0; k < 4; ++k)
            xsum[k] = (int)(rs[wo0 + k] + rs[wo0 + k + 1] + rs[wo0 + k + 2]);
        const int fbase = fh * 32 + f0;
        float* op = out + ((n * F_OUT + fbase) * HW + ho) * HW + wo0;
        #pragma unroll
        for (int fl = 0; fl < 4; ++fl) {
            int ws = (int)g_wsum[fbase + fl];
            float4 o;
            o.x = s * (float)(2 * (int)va[fl].x - ws - xsum[0]);
            o.y = s * (float)(2 * (int)va[fl].y - ws - xsum[1]);
            o.z = s * (float)(2 * (int)va[fl].z - ws - xsum[2]);
            o.w = s * (float)(2 * (int)va[fl].w - ws - xsum[3]);
            *(float4*)(op + fl * HW * HW) = o;
        }
    }
#undef RSLOT
#undef RADD
#undef RSTORE

    // completion ticket: last work block resets counters for the next launch
    __syncthreads();
    if (tid == 0) {
        unsigned v = atomicAdd(&g_fin, 1u);
        if (v == (unsigned)(WB - 1)) {
            g_cnt  = 0u;
            g_done = 0u;
            g_fin  = 0u;
            __threadfence();
        }
    }
}

extern "C" void kernel_launch(void* const* d_in, const int* in_sizes, int n_in,
                              void* d_out, int out_size) {
    const float* x = (const float*)d_in[0];
    const float* W = (const float*)d_in[1];
    float* out = (float*)d_out;

    cudaFuncSetAttribute(k_fused, cudaFuncAttributeMaxDynamicSharedMemorySize,
                         SMEM_BYTES);
    k_fused<<<GRID, THREADS, SMEM_BYTES>>>(x, W, out);
}